// round 17
// baseline (speedup 1.0000x reference)
#include <cuda_runtime.h>
#include <math.h>
#include <stdint.h>

// TimeLSTMHyp: B=64, S=128, H=I=512
//  1) Precompute mobius_matvec(U_g, x): FFMA2 GEMM (exact fp32) + scaling pass (stores ||mu_g||).
//  2) 128 captured steps:
//       gemm_step: z = [h|c] @ Wbig^T, tf32 mma m16n8k8, 8 warps/block (m,k,n split), split-K=8
//       elem_step: Poincare-ball math in 4 reduction rounds (analytic Mobius algebra).

#define MIN_NORM 1e-15f
#define KSLICES 8

// ---------------- static device scratch ----------------
__device__ float g_mu[8192u * 2048u];        // mobius_matvec(U_g, x): [b*128+s][g*512+j] (64 MB)
__device__ float g_tmu[8192u * 4u];          // per-row per-gate ||mu_g||
__device__ float g_wbig[2560 * 512];         // tf32-rounded: rows 0..2047 gate-major W_all; 2048..2559 W_d
__device__ float g_z[KSLICES * 64 * 2560];   // split-K partials per step
__device__ float g_h[64 * 512];
__device__ float g_c[64 * 512];

// ---------------- helpers ----------------
__device__ __forceinline__ float artanhc(float x) {
    x = fminf(fmaxf(x, -1.0f + 1e-5f), 1.0f - 1e-5f);
    return atanhf(x);
}
__device__ __forceinline__ float clampn(float sumsq) {
    return fmaxf(sqrtf(fmaxf(sumsq, 0.0f)), MIN_NORM);
}
__device__ __forceinline__ float sigm(float x) { return 1.0f / (1.0f + expf(-x)); }

__device__ __forceinline__ float cvt_tf32(float x) {
    uint32_t r;
    asm("cvt.rna.tf32.f32 %0, %1;" : "=r"(r) : "f"(x));
    return __uint_as_float(r);
}

// packed f32x2 (FFMA2) helpers — exact-fp32 precompute GEMM
__device__ __forceinline__ unsigned long long dup_f32(float x) {
    unsigned long long r;
    asm("mov.b64 %0, {%1, %1};" : "=l"(r) : "f"(x));
    return r;
}
__device__ __forceinline__ void fma_x2(unsigned long long& d, unsigned long long a, unsigned long long b) {
    asm("fma.rn.f32x2 %0, %1, %2, %0;" : "+l"(d) : "l"(a), "l"(b));
}
__device__ __forceinline__ float2 unpack_x2(unsigned long long v) {
    float2 r;
    asm("mov.b64 {%0, %1}, %2;" : "=f"(r.x), "=f"(r.y) : "l"(v));
    return r;
}

template <int N>
__device__ __forceinline__ void block_reduce_sum(float* v) {
    __shared__ float sh[N][17];
    const int lane = threadIdx.x & 31;
    const int wid  = threadIdx.x >> 5;
    #pragma unroll
    for (int i = 0; i < N; i++) {
        float x = v[i];
        #pragma unroll
        for (int o = 16; o > 0; o >>= 1) x += __shfl_xor_sync(0xffffffffu, x, o);
        if (lane == 0) sh[i][wid] = x;
    }
    __syncthreads();
    if (wid == 0) {
        const int nw = blockDim.x >> 5;
        #pragma unroll
        for (int i = 0; i < N; i++) {
            float x = (lane < nw) ? sh[i][lane] : 0.0f;
            #pragma unroll
            for (int o = 8; o > 0; o >>= 1) x += __shfl_xor_sync(0xffffffffu, x, o);
            if (lane == 0) sh[i][16] = x;
        }
    }
    __syncthreads();
    #pragma unroll
    for (int i = 0; i < N; i++) v[i] = sh[i][16];
    __syncthreads();
}

// ---------------- weight rearrangement (+ tf32 rounding) ----------------
__global__ void prep_w(const float* __restrict__ Wall, const float* __restrict__ Wd) {
    int idx = blockIdx.x * blockDim.x + threadIdx.x;
    if (idx >= 2560 * 512) return;
    int m = idx >> 9, k = idx & 511;
    float v;
    if (m < 2048) {
        int g = m >> 9, jj = m & 511;
        v = Wall[jj * 2048 + (g << 9) + k];
    } else {
        v = Wd[(m - 2048) * 512 + k];
    }
    g_wbig[idx] = cvt_tf32(v);
}

// ---------------- precompute GEMM (exact fp32, FFMA2) ----------------
__global__ void __launch_bounds__(256) gemm_pre(const float* __restrict__ A, const float* __restrict__ U) {
    __shared__ float As[16][132];
    __shared__ float Bs[16][132];
    const int bx = blockIdx.x;
    const int by = blockIdx.y;
    const int tid = threadIdx.x;
    const int lr  = tid >> 1;
    const int lc8 = (tid & 1) << 3;
    const float* Ar = A + (size_t)(by * 128 + lr) * 512 + lc8;
    const float* Ur = U + (size_t)(bx * 128 + lr) * 512 + lc8;
    const int ty = tid >> 4, tx = tid & 15;

    unsigned long long acc[4][8];
    #pragma unroll
    for (int i = 0; i < 4; i++)
        #pragma unroll
        for (int j = 0; j < 8; j++) acc[i][j] = 0ull;

    for (int k0 = 0; k0 < 512; k0 += 16) {
        float4 a0 = *(const float4*)(Ar + k0);
        float4 a1 = *(const float4*)(Ar + k0 + 4);
        float4 b0 = *(const float4*)(Ur + k0);
        float4 b1 = *(const float4*)(Ur + k0 + 4);
        __syncthreads();
        As[lc8 + 0][lr] = a0.x; As[lc8 + 1][lr] = a0.y; As[lc8 + 2][lr] = a0.z; As[lc8 + 3][lr] = a0.w;
        As[lc8 + 4][lr] = a1.x; As[lc8 + 5][lr] = a1.y; As[lc8 + 6][lr] = a1.z; As[lc8 + 7][lr] = a1.w;
        Bs[lc8 + 0][lr] = b0.x; Bs[lc8 + 1][lr] = b0.y; Bs[lc8 + 2][lr] = b0.z; Bs[lc8 + 3][lr] = b0.w;
        Bs[lc8 + 4][lr] = b1.x; Bs[lc8 + 5][lr] = b1.y; Bs[lc8 + 6][lr] = b1.z; Bs[lc8 + 7][lr] = b1.w;
        __syncthreads();
        #pragma unroll
        for (int kk = 0; kk < 16; kk++) {
            ulonglong2 apA = *(const ulonglong2*)&As[kk][ty * 8];
            ulonglong2 apB = *(const ulonglong2*)&As[kk][ty * 8 + 4];
            #pragma unroll
            for (int j = 0; j < 8; j++) {
                unsigned long long bd = dup_f32(Bs[kk][tx + 16 * j]);
                fma_x2(acc[0][j], apA.x, bd);
                fma_x2(acc[1][j], apA.y, bd);
                fma_x2(acc[2][j], apB.x, bd);
                fma_x2(acc[3][j], apB.y, bd);
            }
        }
    }
    float* C = g_mu + (size_t)(by * 128 + ty * 8) * 2048 + bx * 128 + tx;
    #pragma unroll
    for (int ip = 0; ip < 4; ip++) {
        #pragma unroll
        for (int j = 0; j < 8; j++) {
            float2 v = unpack_x2(acc[ip][j]);
            C[(size_t)(2 * ip + 0) * 2048 + j * 16] = v.x;
            C[(size_t)(2 * ip + 1) * 2048 + j * 16] = v.y;
        }
    }
}

// ---------------- scale precomputed mu + store analytic norms ----------------
__global__ void scale_mu(const float* __restrict__ X) {
    const int r = blockIdx.x;
    const int j = threadIdx.x;
    float xj = X[(size_t)r * 512 + j];
    float* mrow = g_mu + (size_t)r * 2048;
    float m0 = mrow[j], m1 = mrow[512 + j], m2 = mrow[1024 + j], m3 = mrow[1536 + j];
    float v[5] = {xj * xj, m0 * m0, m1 * m1, m2 * m2, m3 * m3};
    block_reduce_sum<5>(v);
    float xn = clampn(v[0]);
    float at = artanhc(xn);
    float n0 = clampn(v[1]); float t0 = tanhf(n0 / xn * at); mrow[j]        = t0 / n0 * m0;
    float n1 = clampn(v[2]); float t1 = tanhf(n1 / xn * at); mrow[512 + j]  = t1 / n1 * m1;
    float n2 = clampn(v[3]); float t2 = tanhf(n2 / xn * at); mrow[1024 + j] = t2 / n2 * m2;
    float n3 = clampn(v[4]); float t3 = tanhf(n3 / xn * at); mrow[1536 + j] = t3 / n3 * m3;
    if (j == 0) {
        g_tmu[r * 4 + 0] = t0; g_tmu[r * 4 + 1] = t1;
        g_tmu[r * 4 + 2] = t2; g_tmu[r * 4 + 3] = t3;
    }
}

// ---------------- per-step GEMM: z = [h|c] @ Wbig^T, tf32 mma, split-K=8 ----------------
// grid (40, 8), 256 threads = 8 warps: w = (mh, kh, nh). Warp tile m32 x n32 x k32.
// k-halves combined via smem scratch (full 64-col width!); output written by kh=0 warps.
__global__ void __launch_bounds__(256) gemm_step() {
    __shared__ float a_s[64][68];
    __shared__ float b_s[64][68];
    __shared__ float s_s[64][66];   // k-split partial scratch: 64 rows x 64 cols (+2 pad)
    const int ct  = blockIdx.x;     // 0..39
    const int kc  = blockIdx.y;     // 0..7
    const int tid = threadIdx.x;
    const int col0 = ct * 64;
    const float* Aq = ((ct < 32) ? g_h : g_c) + kc * 64;
    const float* Bq = g_wbig + (size_t)col0 * 512 + kc * 64;

    // stage A (tf32-round) and B: 64x64 each, 4 float4 per thread per matrix
    #pragma unroll
    for (int i = 0; i < 4; i++) {
        int q = tid + i * 256;               // 0..1023
        int r = q >> 4, c4 = (q & 15) << 2;
        float4 a = *(const float4*)(Aq + (size_t)r * 512 + c4);
        a.x = cvt_tf32(a.x); a.y = cvt_tf32(a.y); a.z = cvt_tf32(a.z); a.w = cvt_tf32(a.w);
        *(float4*)&a_s[r][c4] = a;
        *(float4*)&b_s[r][c4] = *(const float4*)(Bq + (size_t)r * 512 + c4);
    }
    __syncthreads();

    const int w    = tid >> 5;
    const int lane = tid & 31;
    const int gid  = lane >> 2;
    const int tig  = lane & 3;
    const int mh = w & 1, kh = (w >> 1) & 1, nh = (w >> 2) & 1;
    const int m0 = mh * 32, n0 = nh * 32, kb = kh * 32;

    float acc[2][4][4];
    #pragma unroll
    for (int mt = 0; mt < 2; mt++)
        #pragma unroll
        for (int nt = 0; nt < 4; nt++)
            #pragma unroll
            for (int p = 0; p < 4; p++) acc[mt][nt][p] = 0.0f;

    #pragma unroll
    for (int ks = 0; ks < 4; ks++) {
        const int k0 = kb + ks * 8;
        uint32_t bf0[4], bf1[4];
        #pragma unroll
        for (int nt = 0; nt < 4; nt++) {
            bf0[nt] = __float_as_uint(b_s[n0 + 8 * nt + gid][k0 + tig]);
            bf1[nt] = __float_as_uint(b_s[n0 + 8 * nt + gid][k0 + tig + 4]);
        }
        #pragma unroll
        for (int mt = 0; mt < 2; mt++) {
            const int mr = m0 + 16 * mt + gid;
            uint32_t a0 = __float_as_uint(a_s[mr    ][k0 + tig    ]);
            uint32_t a1 = __float_as_uint(a_s[mr + 8][k0 + tig    ]);
            uint32_t a2 = __float_as_uint(a_s[mr    ][k0 + tig + 4]);
            uint32_t a3 = __float_as_uint(a_s[mr + 8][k0 + tig + 4]);
            #pragma unroll
            for (int nt = 0; nt < 4; nt++) {
                asm volatile(
                    "mma.sync.aligned.m16n8k8.row.col.f32.tf32.tf32.f32 "
                    "{%0,%1,%2,%3}, {%4,%5,%6,%7}, {%8,%9}, {%0,%1,%2,%3};"
                    : "+f"(acc[mt][nt][0]), "+f"(acc[mt][nt][1]),
                      "+f"(acc[mt][nt][2]), "+f"(acc[mt][nt][3])
                    : "r"(a0), "r"(a1), "r"(a2), "r"(a3), "r"(bf0[nt]), "r"(bf1[nt]));
            }
        }
    }

    if (kh == 1) {   // publish partials (cc up to 62 -> needs 64-wide scratch)
        #pragma unroll
        for (int mt = 0; mt < 2; mt++)
            #pragma unroll
            for (int nt = 0; nt < 4; nt++) {
                const int r0 = m0 + 16 * mt + gid;
                const int cc = n0 + 8 * nt + 2 * tig;
                *(float2*)&s_s[r0    ][cc] = make_float2(acc[mt][nt][0], acc[mt][nt][1]);
                *(float2*)&s_s[r0 + 8][cc] = make_float2(acc[mt][nt][2], acc[mt][nt][3]);
            }
    }
    __syncthreads();
    if (kh == 0) {   // combine and write z slice
        float* Z = g_z + (size_t)kc * 64 * 2560 + col0;
        #pragma unroll
        for (int mt = 0; mt < 2; mt++)
            #pragma unroll
            for (int nt = 0; nt < 4; nt++) {
                const int r0 = m0 + 16 * mt + gid;
                const int cc = n0 + 8 * nt + 2 * tig;
                float2 p = *(const float2*)&s_s[r0    ][cc];
                float2 q = *(const float2*)&s_s[r0 + 8][cc];
                *(float2*)&Z[(size_t)r0 * 2560 + cc]       = make_float2(acc[mt][nt][0] + p.x, acc[mt][nt][1] + p.y);
                *(float2*)&Z[(size_t)(r0 + 8) * 2560 + cc] = make_float2(acc[mt][nt][2] + q.x, acc[mt][nt][3] + q.y);
            }
    }
}

// ---------------- per-step elementwise: 4 reduction rounds (analytic Mobius algebra) ----------------
__global__ void __launch_bounds__(512) elem_step(int step, const float* __restrict__ ts, float* __restrict__ out) {
    const int b = blockIdx.x;
    const int j = threadIdx.x;
    const float t = ts[b * 128 + step];
    const float cj = g_c[b * 512 + j];
    const float hj = g_h[b * 512 + j];

    float zg[4] = {0.f, 0.f, 0.f, 0.f};
    float mcd = 0.f;
    #pragma unroll
    for (int s = 0; s < KSLICES; s++) {
        const float* zp = g_z + (size_t)s * 64 * 2560 + (size_t)b * 2560;
        #pragma unroll
        for (int g = 0; g < 4; g++) zg[g] += zp[g * 512 + j];
        mcd += zp[2048 + j];
    }
    const size_t row = (size_t)b * 128 + step;
    const float* mup = g_mu + row * 2048;
    float mug[4], tmu[4];
    #pragma unroll
    for (int g = 0; g < 4; g++) { mug[g] = mup[g * 512 + j]; tmu[g] = g_tmu[row * 4 + g]; }

    // R1: ||c||^2, ||h||^2, ||mcd||^2, ||z_g||^2 x4, <z_g,mu_g> x4  (11)
    float r1[11] = {cj * cj, hj * hj, mcd * mcd,
                    zg[0] * zg[0], zg[1] * zg[1], zg[2] * zg[2], zg[3] * zg[3],
                    zg[0] * mug[0], zg[1] * mug[1], zg[2] * mug[2], zg[3] * mug[3]};
    block_reduce_sum<11>(r1);
    const float c2 = r1[0];
    const float cn = clampn(c2), hn = clampn(r1[1]), mcdn = clampn(r1[2]);
    const float athn = artanhc(hn);
    const float alpha_m = tanhf(mcdn / cn * artanhc(cn)) / mcdn;   // M1 = alpha_m*mcd
    const float M1n = fmaxf(fabsf(alpha_m) * mcdn, MIN_NORM);
    const float gamma = artanhc(M1n) / M1n * alpha_m;
    const float T = tanhf(gamma * mcd);                            // tanh(logmap0(M1))
    float sg[4];
    #pragma unroll
    for (int g = 0; g < 4; g++) {   // s_g = mobius_add((tgh/zn)*z_g, mu_g)
        float zn = clampn(r1[3 + g]);
        float tgh = tanhf(zn / hn * athn);
        float wc = tgh / zn;
        float x2 = tgh * tgh;
        float y2 = tmu[g] * tmu[g];
        float xy = wc * r1[7 + g];
        float den = fmaxf(1.f + 2.f * xy + x2 * y2, MIN_NORM);
        sg[g] = ((1.f + 2.f * xy + y2) * wc * zg[g] + (1.f - x2) * mug[g]) / den;
    }

    // R2: ||T||^2, ||s_g||^2 x4  (5)
    float r2[5] = {T * T, sg[0] * sg[0], sg[1] * sg[1], sg[2] * sg[2], sg[3] * sg[3]};
    block_reduce_sum<5>(r2);
    const float Tn = clampn(r2[0]);
    const float cs1n = tanhf(Tn);                 // analytic ||c_s1||
    const float cs1 = cs1n / Tn * T;              // c_s1 = expmap0(T)
    const float cs1_2 = cs1n * cs1n;
    float gate[4];
    #pragma unroll
    for (int g = 0; g < 4; g++) {
        float sn = clampn(r2[1 + g]);
        gate[g] = sigm(artanhc(sn) / sn * sg[g]);
    }
    const float gf = gate[0], gi = gate[1], go = gate[2], ctm = gate[3];
    out[row * 512 + j] = go;

    // R3 (8): d1=<cs1,c>, ||ctm||^2, ||ict||^2, G11, G12, G22, H1, H2
    const float ict = gi * ctm;
    const float gf2 = gf * gf;
    const float ictgf = ict * gf;
    float r3[8] = {cs1 * cj, ctm * ctm, ict * ict,
                   gf2 * cs1 * cs1, gf2 * cs1 * cj, gf2 * cj * cj,
                   ictgf * cs1, ictgf * cj};
    block_reduce_sum<8>(r3);
    const float d1 = r3[0];
    const float xy1 = -d1;

    // c_s2 = pw_mul(c_s1, t): scalar chain
    const float ta = fabsf(t);
    const float xn_t  = fmaxf(ta * 22.62741699796952f, MIN_NORM);   // sqrt(512)
    const float wxn_t = fmaxf(ta * cs1n, MIN_NORM);
    const float cs2n = tanhf(wxn_t / xn_t * artanhc(xn_t));
    const float s = cs2n / wxn_t * t;            // c_s2 = s * c_s1
    const float cs2sq = cs2n * cs2n;

    // c_l = mobius_add(-c_s1, c) = a_cl*cs1 + b_cl*c
    const float A4 = 1.f + 2.f * xy1 + c2;
    const float B4 = 1.f - cs1_2;
    const float den4 = fmaxf(1.f + 2.f * xy1 + cs1_2 * c2, MIN_NORM);
    const float a_cl = -A4 / den4, b_cl = B4 / den4;
    const float cln2 = a_cl * a_cl * cs1_2 + 2.f * a_cl * b_cl * d1 + b_cl * b_cl * c2;
    // c_adj = mobius_add(c_l, c_s2) = alp*cs1 + bet*c
    const float xy5 = s * (a_cl * cs1_2 + b_cl * d1);
    const float A5 = 1.f + 2.f * xy5 + cs2sq;
    const float B5 = 1.f - cln2;
    const float den5 = fmaxf(1.f + 2.f * xy5 + cln2 * cs2sq, MIN_NORM);
    const float alp = (A5 * a_cl + B5 * s) / den5;
    const float bet = A5 * b_cl / den5;
    // analytic norms via R3 scalars
    const float cadjn = clampn(alp * alp * cs1_2 + 2.f * alp * bet * d1 + bet * bet * c2);
    const float fcan  = clampn(alp * alp * r3[3] + 2.f * alp * bet * r3[4] + bet * bet * r3[5]);
    // Q = pw_mul(f, c_adj) = qs * gf * cadj
    const float Qn = tanhf(fcan / cadjn * artanhc(cadjn));
    const float qs = Qn / fcan;
    const float Q2 = Qn * Qn;
    // P = pw_mul(i, c_tmp) = p * ict
    const float ctn = clampn(r3[1]), ictn = clampn(r3[2]);
    const float Pn = tanhf(ictn / ctn * artanhc(ctn));
    const float p = Pn / ictn;
    const float P2s = Pn * Pn;
    // <P,Q> analytic
    const float PQ = p * qs * (alp * r3[6] + bet * r3[7]);
    // c_new = mobius_add(P, Q)
    const float den7 = fmaxf(1.f + 2.f * PQ + P2s * Q2, MIN_NORM);
    const float A7 = (1.f + 2.f * PQ + Q2) / den7;
    const float B7 = (1.f - P2s) / den7;
    const float cadj = alp * cs1 + bet * cj;
    const float cnew = A7 * p * ict + B7 * qs * gf * cadj;

    // R4: ||u||^2, ||go*u||^2 with u = tanh(cnew)  (2)
    const float u = tanhf(cnew);
    const float gou = go * u;
    float r4[2] = {u * u, gou * gou};
    block_reduce_sum<2>(r4);
    const float un = clampn(r4[0]);
    const float en_exact = tanhf(un);
    const float iun = en_exact / un;             // e = iun * u
    const float en = fmaxf(en_exact, MIN_NORM);
    const float oen = fmaxf(iun * sqrtf(fmaxf(r4[1], 0.f)), MIN_NORM);   // ||o*e||
    const float hnew = tanhf(oen / en * artanhc(en)) / oen * (go * iun * u);

    g_h[b * 512 + j] = hnew;
    g_c[b * 512 + j] = cnew;
    if (step == 127) {
        out[(size_t)64 * 128 * 512 + (size_t)b * 512 + j] = hnew;
        out[(size_t)64 * 128 * 512 + (size_t)64 * 512 + (size_t)b * 512 + j] = cnew;
    }
}

// ---------------- launch ----------------
extern "C" void kernel_launch(void* const* d_in, const int* in_sizes, int n_in,
                              void* d_out, int out_size) {
    const float* inputs = (const float*)d_in[0];
    const float* ts     = (const float*)d_in[1];
    const float* h0     = (const float*)d_in[2];
    const float* c0     = (const float*)d_in[3];
    const float* Wall   = (const float*)d_in[4];
    const float* Uall   = (const float*)d_in[5];
    const float* Wd     = (const float*)d_in[6];
    float* out = (float*)d_out;

    cudaMemcpyToSymbolAsync(g_h, h0, 64 * 512 * sizeof(float), 0, cudaMemcpyDeviceToDevice, 0);
    cudaMemcpyToSymbolAsync(g_c, c0, 64 * 512 * sizeof(float), 0, cudaMemcpyDeviceToDevice, 0);

    prep_w<<<(2560 * 512 + 255) / 256, 256>>>(Wall, Wd);
    gemm_pre<<<dim3(16, 64), 256>>>(inputs, Uall);
    scale_mu<<<8192, 512>>>(inputs);

    for (int t = 0; t < 128; t++) {
        gemm_step<<<dim3(40, 8), 256>>>();
        elem_step<<<64, 512>>>(t, ts, out);
    }
}